// round 2
// baseline (speedup 1.0000x reference)
#include <cuda_runtime.h>
#include <cstdint>

// Problem constants (fixed by setup_inputs)
#define NB 64   // batch

// Integer accumulators => deterministic (integer atomics are associative).
__device__ int g_cs_y[NB];
__device__ int g_cs_x[NB];
__device__ int g_cnt;

__global__ void init_kernel() {
    int t = threadIdx.x;
    if (t < NB) { g_cs_y[t] = 0; g_cs_x[t] = 0; }
    if (t == 0) g_cnt = 0;
}

template <int H, int W, int R>
__device__ __forceinline__ void peak_level(const float* __restrict__ p, int n, int tile) {
    constexpr int IW = W - 2;
    constexpr int IH = H - 2;
    // last channel (channel 2 of 3)
    const float* __restrict__ h = p + ((size_t)n * 3 + 2) * (size_t)(H * W);

    int t = tile * 256 + threadIdx.x;
    int sy = 0, sx = 0, c = 0;
    if (t < IH * IW) {
        int i = 1 + t / IW;     // constexpr divisor -> mul/shift
        int j = 1 + t % IW;
        const float* rm = h + (size_t)(i - 1) * W + j;
        const float* rc = h + (size_t)i * W + j;
        const float* rp = h + (size_t)(i + 1) * W + j;
        float cv = rc[0];
        bool peak = (cv > rm[-1]) && (cv > rm[0]) && (cv > rm[1]) &&
                    (cv > rc[-1]) && (cv > rc[1]) &&
                    (cv > rp[-1]) && (cv > rp[0]) && (cv > rp[1]);
        if (peak) { sy = R * i; sx = R * j; c = 1; }
    }

    // warp reduce (int, exact)
    sy = __reduce_add_sync(0xffffffffu, sy);
    sx = __reduce_add_sync(0xffffffffu, sx);
    c  = __reduce_add_sync(0xffffffffu, c);

    __shared__ int s[3][8];
    int w = threadIdx.x >> 5, lane = threadIdx.x & 31;
    if (lane == 0) { s[0][w] = sy; s[1][w] = sx; s[2][w] = c; }
    __syncthreads();
    if (threadIdx.x == 0) {
        int ty = 0, tx = 0, tc = 0;
#pragma unroll
        for (int k = 0; k < 8; k++) { ty += s[0][k]; tx += s[1][k]; tc += s[2][k]; }
        atomicAdd(&g_cs_y[n], ty);
        atomicAdd(&g_cs_x[n], tx);
        atomicAdd(&g_cnt, tc);
    }
}

// tiles per image: L1 (254*254)/256 -> 253, L2 (126*126)/256 -> 63, L3 (62*62)/256 -> 16
#define T1 253
#define T2 63
#define T3 16
#define TTOT (T1 + T2 + T3)   // 332

__global__ void peak_kernel(const float* __restrict__ p1,
                            const float* __restrict__ p2,
                            const float* __restrict__ p3) {
    int n  = blockIdx.y;
    int tb = blockIdx.x;
    if (tb < T1) {
        peak_level<256, 256, 4>(p1, n, tb);
    } else if (tb < T1 + T2) {
        peak_level<128, 128, 8>(p2, n, tb - T1);
    } else {
        peak_level<64, 64, 16>(p3, n, tb - (T1 + T2));
    }
}

__global__ void final_kernel(const float* __restrict__ target, float* __restrict__ out) {
    __shared__ float s_sly[NB], s_slx[NB], s_cy[NB], s_cx[NB], s_t0[NB], s_t1[NB];
    int n = threadIdx.x;
    if (n < NB) {
        const float* t = target + (size_t)n * 32 * 5;
        float ts0 = 0.f, ts1 = 0.f;
#pragma unroll
        for (int k = 0; k < 32; k++) {
            ts0 += 0.5f * (t[k * 5 + 2] + t[k * 5 + 0]);
            ts1 += 0.5f * (t[k * 5 + 3] + t[k * 5 + 1]);
        }
        float cy = (float)g_cs_y[n];
        float cx = (float)g_cs_x[n];
        float dy = fabsf(cy - ts0);
        float dx = fabsf(cx - ts1);
        s_sly[n] = (dy < 1.f) ? 0.5f * dy * dy : dy - 0.5f;
        s_slx[n] = (dx < 1.f) ? 0.5f * dx * dx : dx - 0.5f;
        s_cy[n] = cy; s_cx[n] = cx; s_t0[n] = ts0; s_t1[n] = ts1;
    }
    __syncthreads();
    if (threadIdx.x == 0) {
        float offx = 0.f, offy = 0.f, cst0 = 0.f, cst1 = 0.f, tst0 = 0.f, tst1 = 0.f;
        for (int k = 0; k < NB; k++) {
            offx += s_sly[k]; offy += s_slx[k];
            cst0 += s_cy[k];  cst1 += s_cx[k];
            tst0 += s_t0[k];  tst1 += s_t1[k];
        }
        float sgx = offx / fabsf(offx);
        float sgy = offy / fabsf(offy);
        out[0] = (sgx * (cst0 - tst0) + sgy * (cst1 - tst1)) / (float)g_cnt;
    }
}

extern "C" void kernel_launch(void* const* d_in, const int* in_sizes, int n_in,
                              void* d_out, int out_size) {
    const float* p1  = (const float*)d_in[0];
    const float* p2  = (const float*)d_in[1];
    const float* p3  = (const float*)d_in[2];
    const float* tgt = (const float*)d_in[3];
    float* out = (float*)d_out;

    init_kernel<<<1, 64>>>();
    dim3 grid(TTOT, NB);
    peak_kernel<<<grid, 256>>>(p1, p2, p3);
    final_kernel<<<1, 64>>>(tgt, out);
}

// round 3
// speedup vs baseline: 2.3787x; 2.3787x over previous
#include <cuda_runtime.h>
#include <cstdint>

#define NB 64       // batch
#define NSLOT 11    // 8 (L1 strips) + 2 (L2 strips) + 1 (L3)

// Per-(image,slot) exact integer partials: [y-sum, x-sum, count].
// Every entry is written on every run -> no init kernel needed, deterministic.
__device__ int g_part[NB][NSLOT][3];

// Load 6 contiguous values centered on this thread's 4-column group:
// v[0] = col 4cg-1, v[1..4] = cols 4cg..4cg+3 (one LDG.128), v[5] = col 4cg+4.
template <int W, int CG>
__device__ __forceinline__ void load_row6(const float* __restrict__ h, int row,
                                          int cg, float (&v)[6]) {
    const float* r = h + (size_t)row * W + 4 * cg;
    float4 C = *reinterpret_cast<const float4*>(r);
    v[1] = C.x; v[2] = C.y; v[3] = C.z; v[4] = C.w;
    v[0] = (cg > 0)      ? r[-1] : 0.f;
    v[5] = (cg < CG - 1) ? r[4]  : 0.f;
}

// Thread computes peaks for 4 columns x K rows with rolling 3-row registers.
template <int H, int W, int Rm, int CG, int K>
__device__ __forceinline__ void peak_strip(const float* __restrict__ p, int n,
                                           int base_i, int cg,
                                           int& sy, int& sx, int& cnt) {
    const float* __restrict__ h = p + ((size_t)n * 3 + 2) * (size_t)(H * W);
    float a[6], b[6], c[6];
    load_row6<W, CG>(h, base_i > 0 ? base_i - 1 : 0, cg, a);
    load_row6<W, CG>(h, base_i, cg, b);
#pragma unroll
    for (int r = 0; r < K; r++) {
        int i = base_i + r;
        int nr = (i + 1 > H - 1) ? H - 1 : i + 1;
        load_row6<W, CG>(h, nr, cg, c);
        if (i >= 1 && i <= H - 2) {
#pragma unroll
            for (int k = 0; k < 4; k++) {
                int j = 4 * cg + k;
                bool jv = (j >= 1) && (j <= W - 2);
                float m = fmaxf(fmaxf(fmaxf(a[k], a[k + 1]), fmaxf(a[k + 2], b[k])),
                                fmaxf(fmaxf(b[k + 2], c[k]), fmaxf(c[k + 1], c[k + 2])));
                if (jv && (b[k + 1] > m)) { sy += Rm * i; sx += Rm * j; cnt++; }
            }
        }
#pragma unroll
        for (int q = 0; q < 6; q++) { a[q] = b[q]; b[q] = c[q]; }
    }
}

__global__ void peak_kernel(const float* __restrict__ p1,
                            const float* __restrict__ p2,
                            const float* __restrict__ p3) {
    int n = blockIdx.y;
    int slot = blockIdx.x;
    int tid = threadIdx.x;
    int sy = 0, sx = 0, cnt = 0;

    if (slot < 8) {
        // 256x256: 64 col-groups x 4 row-teams; strip = 32 rows, team = 8 rows
        int cg = tid & 63, rt = tid >> 6;
        peak_strip<256, 256, 4, 64, 8>(p1, n, slot * 32 + rt * 8, cg, sy, sx, cnt);
    } else if (slot < 10) {
        // 128x128: 32 col-groups x 8 row-teams; strip = 64 rows, team = 8 rows
        int cg = tid & 31, rt = tid >> 5;
        peak_strip<128, 128, 8, 32, 8>(p2, n, (slot - 8) * 64 + rt * 8, cg, sy, sx, cnt);
    } else {
        // 64x64: 16 col-groups x 16 row-teams; team = 4 rows (covers 64 rows)
        int cg = tid & 15, rt = tid >> 4;
        peak_strip<64, 64, 16, 16, 4>(p3, n, rt * 4, cg, sy, sx, cnt);
    }

    // exact integer block reduction
    sy  = __reduce_add_sync(0xffffffffu, sy);
    sx  = __reduce_add_sync(0xffffffffu, sx);
    cnt = __reduce_add_sync(0xffffffffu, cnt);

    __shared__ int s[3][8];
    int w = threadIdx.x >> 5, lane = threadIdx.x & 31;
    if (lane == 0) { s[0][w] = sy; s[1][w] = sx; s[2][w] = cnt; }
    __syncthreads();
    if (threadIdx.x == 0) {
        int ty = 0, tx = 0, tc = 0;
#pragma unroll
        for (int k = 0; k < 8; k++) { ty += s[0][k]; tx += s[1][k]; tc += s[2][k]; }
        g_part[n][slot][0] = ty;
        g_part[n][slot][1] = tx;
        g_part[n][slot][2] = tc;
    }
}

__global__ void final_kernel(const float* __restrict__ target, float* __restrict__ out) {
    __shared__ float s_sly[NB], s_slx[NB], s_cy[NB], s_cx[NB], s_t0[NB], s_t1[NB];
    __shared__ int s_cnt[NB];
    int n = threadIdx.x;
    if (n < NB) {
        int cyi = 0, cxi = 0, ci = 0;
#pragma unroll
        for (int s = 0; s < NSLOT; s++) {
            cyi += g_part[n][s][0];
            cxi += g_part[n][s][1];
            ci  += g_part[n][s][2];
        }
        const float* t = target + (size_t)n * 32 * 5;
        float ts0 = 0.f, ts1 = 0.f;
#pragma unroll
        for (int k = 0; k < 32; k++) {
            ts0 += 0.5f * (t[k * 5 + 2] + t[k * 5 + 0]);
            ts1 += 0.5f * (t[k * 5 + 3] + t[k * 5 + 1]);
        }
        float cy = (float)cyi, cx = (float)cxi;
        float dy = fabsf(cy - ts0);
        float dx = fabsf(cx - ts1);
        s_sly[n] = (dy < 1.f) ? 0.5f * dy * dy : dy - 0.5f;
        s_slx[n] = (dx < 1.f) ? 0.5f * dx * dx : dx - 0.5f;
        s_cy[n] = cy; s_cx[n] = cx; s_t0[n] = ts0; s_t1[n] = ts1;
        s_cnt[n] = ci;
    }
    __syncthreads();
    if (threadIdx.x == 0) {
        float offx = 0.f, offy = 0.f, cst0 = 0.f, cst1 = 0.f, tst0 = 0.f, tst1 = 0.f;
        int pc = 0;
        for (int k = 0; k < NB; k++) {
            offx += s_sly[k]; offy += s_slx[k];
            cst0 += s_cy[k];  cst1 += s_cx[k];
            tst0 += s_t0[k];  tst1 += s_t1[k];
            pc   += s_cnt[k];
        }
        float sgx = offx / fabsf(offx);
        float sgy = offy / fabsf(offy);
        out[0] = (sgx * (cst0 - tst0) + sgy * (cst1 - tst1)) / (float)pc;
    }
}

extern "C" void kernel_launch(void* const* d_in, const int* in_sizes, int n_in,
                              void* d_out, int out_size) {
    const float* p1  = (const float*)d_in[0];
    const float* p2  = (const float*)d_in[1];
    const float* p3  = (const float*)d_in[2];
    const float* tgt = (const float*)d_in[3];
    float* out = (float*)d_out;

    dim3 grid(NSLOT, NB);
    peak_kernel<<<grid, 256>>>(p1, p2, p3);
    final_kernel<<<1, 64>>>(tgt, out);
}

// round 4
// speedup vs baseline: 3.2350x; 1.3600x over previous
#include <cuda_runtime.h>
#include <cstdint>

#define NB 64       // batch
#define NSLOT 11    // 8 (L1 strips) + 2 (L2 strips) + 1 (L3)
#define NBLK (NB * NSLOT)

// Per-(image,slot) exact integer partials [y-sum, x-sum, count] and per-image
// truth-center sums. Every entry rewritten each run -> no init pass needed.
__device__ int   g_part[NB][NSLOT][3];
__device__ float g_tsum[NB][2];
__device__ int   g_ticket;   // zero at load; last block resets to 0 each run

// Load 6 contiguous values centered on this thread's 4-column group:
// v[0] = col 4cg-1, v[1..4] = cols 4cg..4cg+3 (one LDG.128), v[5] = col 4cg+4.
template <int W, int CG>
__device__ __forceinline__ void load_row6(const float* __restrict__ h, int row,
                                          int cg, float (&v)[6]) {
    const float* r = h + (size_t)row * W + 4 * cg;
    float4 C = *reinterpret_cast<const float4*>(r);
    v[1] = C.x; v[2] = C.y; v[3] = C.z; v[4] = C.w;
    v[0] = (cg > 0)      ? r[-1] : 0.f;
    v[5] = (cg < CG - 1) ? r[4]  : 0.f;
}

// Thread computes peaks for 4 columns x K rows with rolling 3-row registers.
template <int H, int W, int Rm, int CG, int K>
__device__ __forceinline__ void peak_strip(const float* __restrict__ p, int n,
                                           int base_i, int cg,
                                           int& sy, int& sx, int& cnt) {
    const float* __restrict__ h = p + ((size_t)n * 3 + 2) * (size_t)(H * W);
    float a[6], b[6], c[6];
    load_row6<W, CG>(h, base_i > 0 ? base_i - 1 : 0, cg, a);
    load_row6<W, CG>(h, base_i, cg, b);
#pragma unroll
    for (int r = 0; r < K; r++) {
        int i = base_i + r;
        int nr = (i + 1 > H - 1) ? H - 1 : i + 1;
        load_row6<W, CG>(h, nr, cg, c);
        if (i >= 1 && i <= H - 2) {
#pragma unroll
            for (int k = 0; k < 4; k++) {
                int j = 4 * cg + k;
                bool jv = (j >= 1) && (j <= W - 2);
                float m = fmaxf(fmaxf(fmaxf(a[k], a[k + 1]), fmaxf(a[k + 2], b[k])),
                                fmaxf(fmaxf(b[k + 2], c[k]), fmaxf(c[k + 1], c[k + 2])));
                if (jv && (b[k + 1] > m)) { sy += Rm * i; sx += Rm * j; cnt++; }
            }
        }
#pragma unroll
        for (int q = 0; q < 6; q++) { a[q] = b[q]; b[q] = c[q]; }
    }
}

__device__ __forceinline__ float warp_sum_f(float v) {
#pragma unroll
    for (int o = 16; o; o >>= 1) v += __shfl_xor_sync(0xffffffffu, v, o);
    return v;
}

__global__ void fused_kernel(const float* __restrict__ p1,
                             const float* __restrict__ p2,
                             const float* __restrict__ p3,
                             const float* __restrict__ target,
                             float* __restrict__ out) {
    int n = blockIdx.y;
    int slot = blockIdx.x;
    int tid = threadIdx.x;
    int sy = 0, sx = 0, cnt = 0;

    // slot-10 blocks (lightest work) also compute the truth-center sums for
    // their image; loads issued first so they overlap the peak loads.
    if (slot == 10 && tid < 32) {
        const float* t = target + (size_t)n * 32 * 5 + (size_t)tid * 5;
        float v0 = 0.5f * (t[2] + t[0]);
        float v1 = 0.5f * (t[3] + t[1]);
        v0 = warp_sum_f(v0);
        v1 = warp_sum_f(v1);
        if (tid == 0) { g_tsum[n][0] = v0; g_tsum[n][1] = v1; }
    }

    if (slot < 8) {
        // 256x256: 64 col-groups x 4 row-teams; strip = 32 rows, team = 8 rows
        int cg = tid & 63, rt = tid >> 6;
        peak_strip<256, 256, 4, 64, 8>(p1, n, slot * 32 + rt * 8, cg, sy, sx, cnt);
    } else if (slot < 10) {
        // 128x128: 32 col-groups x 8 row-teams; strip = 64 rows, team = 8 rows
        int cg = tid & 31, rt = tid >> 5;
        peak_strip<128, 128, 8, 32, 8>(p2, n, (slot - 8) * 64 + rt * 8, cg, sy, sx, cnt);
    } else {
        // 64x64: 16 col-groups x 16 row-teams; team = 4 rows (covers 64 rows)
        int cg = tid & 15, rt = tid >> 4;
        peak_strip<64, 64, 16, 16, 4>(p3, n, rt * 4, cg, sy, sx, cnt);
    }

    // exact integer block reduction
    sy  = __reduce_add_sync(0xffffffffu, sy);
    sx  = __reduce_add_sync(0xffffffffu, sx);
    cnt = __reduce_add_sync(0xffffffffu, cnt);

    __shared__ int s[3][8];
    __shared__ bool is_last;
    int w = tid >> 5, lane = tid & 31;
    if (lane == 0) { s[0][w] = sy; s[1][w] = sx; s[2][w] = cnt; }
    __syncthreads();
    if (tid == 0) {
        int ty = 0, tx = 0, tc = 0;
#pragma unroll
        for (int k = 0; k < 8; k++) { ty += s[0][k]; tx += s[1][k]; tc += s[2][k]; }
        g_part[n][slot][0] = ty;
        g_part[n][slot][1] = tx;
        g_part[n][slot][2] = tc;
        __threadfence();
        int t = atomicAdd(&g_ticket, 1);
        is_last = (t == NBLK - 1);
    }
    __syncthreads();
    if (!is_last) return;

    // ---- epilogue: the elected last block does the loss ----
    if (tid == 0) g_ticket = 0;   // reset for the next graph replay

    __shared__ float r_offx[2], r_offy[2], r_c0[2], r_c1[2], r_t0[2], r_t1[2];
    __shared__ int r_pc[2];

    if (tid < NB) {
        int cyi = 0, cxi = 0, ci = 0;
#pragma unroll
        for (int sl = 0; sl < NSLOT; sl++) {
            cyi += __ldcg(&g_part[tid][sl][0]);
            cxi += __ldcg(&g_part[tid][sl][1]);
            ci  += __ldcg(&g_part[tid][sl][2]);
        }
        float ts0 = __ldcg(&g_tsum[tid][0]);
        float ts1 = __ldcg(&g_tsum[tid][1]);
        float cy = (float)cyi, cx = (float)cxi;
        float dy = fabsf(cy - ts0);
        float dx = fabsf(cx - ts1);
        float sly = (dy < 1.f) ? 0.5f * dy * dy : dy - 0.5f;
        float slx = (dx < 1.f) ? 0.5f * dx * dx : dx - 0.5f;

        float offx = warp_sum_f(sly);
        float offy = warp_sum_f(slx);
        float c0   = warp_sum_f(cy);
        float c1   = warp_sum_f(cx);
        float t0   = warp_sum_f(ts0);
        float t1   = warp_sum_f(ts1);
        int pc = ci;
#pragma unroll
        for (int o = 16; o; o >>= 1) pc += __shfl_xor_sync(0xffffffffu, pc, o);

        if (lane == 0) {
            r_offx[w] = offx; r_offy[w] = offy;
            r_c0[w] = c0; r_c1[w] = c1; r_t0[w] = t0; r_t1[w] = t1;
            r_pc[w] = pc;
        }
    }
    __syncthreads();
    if (tid == 0) {
        float offx = r_offx[0] + r_offx[1];
        float offy = r_offy[0] + r_offy[1];
        float cst0 = r_c0[0] + r_c0[1];
        float cst1 = r_c1[0] + r_c1[1];
        float tst0 = r_t0[0] + r_t0[1];
        float tst1 = r_t1[0] + r_t1[1];
        int pc = r_pc[0] + r_pc[1];
        float sgx = offx / fabsf(offx);
        float sgy = offy / fabsf(offy);
        out[0] = (sgx * (cst0 - tst0) + sgy * (cst1 - tst1)) / (float)pc;
    }
}

extern "C" void kernel_launch(void* const* d_in, const int* in_sizes, int n_in,
                              void* d_out, int out_size) {
    const float* p1  = (const float*)d_in[0];
    const float* p2  = (const float*)d_in[1];
    const float* p3  = (const float*)d_in[2];
    const float* tgt = (const float*)d_in[3];
    float* out = (float*)d_out;

    dim3 grid(NSLOT, NB);
    fused_kernel<<<grid, 256>>>(p1, p2, p3, tgt, out);
}